// round 9
// baseline (speedup 1.0000x reference)
#include <cuda_runtime.h>
#include <cuda_bf16.h>
#include <cstdint>

#define NN 50000
#define NE 600000
#define DD 128
#define NG 64

// ---------------- scratch (device globals; no allocation allowed) ----------------
__device__ float    g_dis[5 * NN];          // plane 0: unweighted, 1..4: per-head (deg -> rsqrt)
__device__ int      g_cnt[NN];
__device__ int      g_fill[NN];
__device__ int      g_rowptr[NN + 1];
__device__ int      g_bsum[64];
__device__ int      g_srcs[NE];
__device__ float    g_norm0[NE];
__device__ float    g_norm4[4 * NE];
__device__ float    g_Wt1[512 * 128];       // Wcat^T  [N=512][K=128] (head h = rows h*128..)
__device__ float    g_Wt2[256 * 512];       // W2^T    [N=256][K=512]
__device__ float    g_Wt3[128 * 256];       // W3^T    [N=128][K=256]
__device__ float    g_bcat[512];
__device__ float    g_bufA[(size_t)NN * 512];
__device__ float    g_bufB[(size_t)NN * 512];
__device__ float    g_psum[NG * DD];
__device__ unsigned g_pmax[NG * DD];
__device__ int      g_pcnt[NG];

// ---------------- helpers ----------------
__device__ __forceinline__ unsigned encf(float f) {
    unsigned b = __float_as_uint(f);
    return (b & 0x80000000u) ? ~b : (b | 0x80000000u);
}
__device__ __forceinline__ float decf(unsigned u) {
    unsigned b = (u & 0x80000000u) ? (u & 0x7FFFFFFFu) : ~u;
    return __uint_as_float(b);
}
__device__ __forceinline__ uint32_t tf32r(float f) {
    uint32_t u;
    asm("cvt.rna.tf32.f32 %0, %1;" : "=r"(u) : "f"(f));
    return u;
}
__device__ __forceinline__ uint32_t smem_u32(const void* p) {
    uint32_t a;
    asm("{ .reg .u64 t; cvta.to.shared.u64 t, %1; cvt.u32.u64 %0, t; }" : "=r"(a) : "l"(p));
    return a;
}
__device__ __forceinline__ void cpa16(uint32_t daddr, const void* src, bool valid) {
    int sz = valid ? 16 : 0;
    asm volatile("cp.async.ca.shared.global [%0], [%1], 16, %2;\n"
                 :: "r"(daddr), "l"(src), "r"(sz) : "memory");
}

// ---------------- zero scratch ----------------
__global__ void zero_all_k() {
    int i = blockIdx.x * blockDim.x + threadIdx.x;
    if (i < 5 * NN) g_dis[i] = 0.0f;
    if (i < NN) { g_cnt[i] = 0; g_fill[i] = 0; }
    if (i < NG * DD) { g_psum[i] = 0.0f; g_pmax[i] = 0u; }
    if (i < NG) g_pcnt[i] = 0;
}

// ---------------- degree + count (plane0 derived from g_cnt later) ----------------
__global__ void degree_k(const int* __restrict__ ei, const float* __restrict__ attr) {
    int e = blockIdx.x * blockDim.x + threadIdx.x;
    if (e >= NE) return;
    int dst = ei[NE + e];
    float4 a = *reinterpret_cast<const float4*>(attr + e * 4);
    atomicAdd(&g_cnt[dst], 1);
    atomicAdd(&g_dis[1 * NN + dst], a.x);
    atomicAdd(&g_dis[2 * NN + dst], a.y);
    atomicAdd(&g_dis[3 * NN + dst], a.z);
    atomicAdd(&g_dis[4 * NN + dst], a.w);
}

__global__ void finalize_dis_k() {
    int i = blockIdx.x * blockDim.x + threadIdx.x;
    if (i >= 5 * NN) return;
    if (i < NN)
        g_dis[i] = rsqrtf((float)g_cnt[i] + 1.0f);        // unweighted: cnt + self loop
    else
        g_dis[i] = rsqrtf(g_dis[i] + 1.0f);               // weighted: +1 self loop
}

// ---------------- 3-phase multi-block scan over 50000 counts ----------------
__global__ void scan1_k() {
    __shared__ int ws[32];
    int b = blockIdx.x, t = threadIdx.x, lane = t & 31, w = t >> 5;
    int i = b * 1024 + t;
    int v = (i < NN) ? g_cnt[i] : 0;
    int inc = v;
#pragma unroll
    for (int off = 1; off < 32; off <<= 1) {
        int x = __shfl_up_sync(0xFFFFFFFFu, inc, off);
        if (lane >= off) inc += x;
    }
    if (lane == 31) ws[w] = inc;
    __syncthreads();
    if (w == 0) {
        int s = ws[lane];
#pragma unroll
        for (int off = 1; off < 32; off <<= 1) {
            int x = __shfl_up_sync(0xFFFFFFFFu, s, off);
            if (lane >= off) s += x;
        }
        ws[lane] = s;
    }
    __syncthreads();
    int pre = (w > 0) ? ws[w - 1] : 0;
    int incl = pre + inc;
    if (i < NN) g_rowptr[i + 1] = incl;
    if (t == 1023) g_bsum[b] = incl;
}
__global__ void scan2_k() {
    __shared__ int s[64];
    int t = threadIdx.x;
    int v = (t < 49) ? g_bsum[t] : 0;
    s[t] = v; __syncthreads();
    for (int off = 1; off < 64; off <<= 1) {
        int x = (t >= off) ? s[t - off] : 0;
        __syncthreads();
        s[t] += x;
        __syncthreads();
    }
    if (t < 49) g_bsum[t] = s[t] - v;   // exclusive
}
__global__ void scan3_k() {
    int b = blockIdx.x, t = threadIdx.x, i = b * 1024 + t;
    if (i < NN) g_rowptr[i + 1] += g_bsum[b];
    if (i == 0) g_rowptr[0] = 0;
}

// ---------------- scatter edges into CSR, precompute norms ----------------
__global__ void scatter_k(const int* __restrict__ ei, const float* __restrict__ attr) {
    int e = blockIdx.x * blockDim.x + threadIdx.x;
    if (e >= NE) return;
    int src = ei[e];
    int dst = ei[NE + e];
    float4 a = *reinterpret_cast<const float4*>(attr + e * 4);
    int pos = g_rowptr[dst] + atomicAdd(&g_fill[dst], 1);
    g_srcs[pos] = src;
    g_norm0[pos] = g_dis[src] * g_dis[dst];
    float4 nv;
    nv.x = g_dis[1 * NN + src] * a.x * g_dis[1 * NN + dst];
    nv.y = g_dis[2 * NN + src] * a.y * g_dis[2 * NN + dst];
    nv.z = g_dis[3 * NN + src] * a.z * g_dis[3 * NN + dst];
    nv.w = g_dis[4 * NN + src] * a.w * g_dis[4 * NN + dst];
    *reinterpret_cast<float4*>(g_norm4 + pos * 4) = nv;
}

// ---------------- weight transposes ----------------
__global__ void pack1_k(const float* __restrict__ WA, const float* __restrict__ WB,
                        const float* __restrict__ WC, const float* __restrict__ WD,
                        const float* __restrict__ bA, const float* __restrict__ bB,
                        const float* __restrict__ bC, const float* __restrict__ bD) {
    int idx = blockIdx.x * blockDim.x + threadIdx.x;   // [0, 512*128)
    if (idx >= 512 * 128) return;
    int k = idx & 127, n = idx >> 7;
    int h = n >> 7, c = n & 127;
    const float* W = (h == 0) ? WA : (h == 1) ? WB : (h == 2) ? WC : WD;
    g_Wt1[idx] = W[k * 128 + c];
    if (k == 0) {
        const float* b = (h == 0) ? bA : (h == 1) ? bB : (h == 2) ? bC : bD;
        g_bcat[n] = b[c];
    }
}
__global__ void pack2_k(const float* __restrict__ W2) {
    int idx = blockIdx.x * blockDim.x + threadIdx.x;   // [0, 256*512)
    if (idx >= 256 * 512) return;
    int k = idx & 511, n = idx >> 9;
    g_Wt2[idx] = W2[k * 256 + n];
}
__global__ void pack3_k(const float* __restrict__ W3) {
    int idx = blockIdx.x * blockDim.x + threadIdx.x;   // [0, 128*256)
    if (idx >= 128 * 256) return;
    int k = idx & 255, n = idx >> 8;
    g_Wt3[idx] = W3[k * 128 + n];
}

// ---------------- fused 4-head aggregation of x (1 warp/node, 128 cols) ----------------
// out planes: out[h*NN*128 + node*128 + c]
__global__ __launch_bounds__(256) void aggx_k(const float* __restrict__ x,
                                              float* __restrict__ out) {
    int node = (blockIdx.x * blockDim.x + threadIdx.x) >> 5;
    if (node >= NN) return;
    int lane = threadIdx.x & 31;
    float sn[4];
#pragma unroll
    for (int h = 0; h < 4; h++) {
        float d = g_dis[(h + 1) * NN + node];
        sn[h] = d * d;                       // self-loop norm = 1/deg_w
    }
    const float* xr = x + (size_t)node * 128;
    float acc[4][4];
#pragma unroll
    for (int j = 0; j < 4; j++) {
        float v = xr[j * 32 + lane];
#pragma unroll
        for (int h = 0; h < 4; h++) acc[h][j] = sn[h] * v;
    }
    int beg = g_rowptr[node], end = g_rowptr[node + 1];
    for (int e = beg; e < end; e++) {
        int s = g_srcs[e];
        float4 nr = *reinterpret_cast<const float4*>(g_norm4 + (size_t)e * 4);
        const float* xs = x + (size_t)s * 128;
        float v0 = xs[lane], v1 = xs[32 + lane], v2 = xs[64 + lane], v3 = xs[96 + lane];
        acc[0][0] = fmaf(nr.x, v0, acc[0][0]); acc[0][1] = fmaf(nr.x, v1, acc[0][1]);
        acc[0][2] = fmaf(nr.x, v2, acc[0][2]); acc[0][3] = fmaf(nr.x, v3, acc[0][3]);
        acc[1][0] = fmaf(nr.y, v0, acc[1][0]); acc[1][1] = fmaf(nr.y, v1, acc[1][1]);
        acc[1][2] = fmaf(nr.y, v2, acc[1][2]); acc[1][3] = fmaf(nr.y, v3, acc[1][3]);
        acc[2][0] = fmaf(nr.z, v0, acc[2][0]); acc[2][1] = fmaf(nr.z, v1, acc[2][1]);
        acc[2][2] = fmaf(nr.z, v2, acc[2][2]); acc[2][3] = fmaf(nr.z, v3, acc[2][3]);
        acc[3][0] = fmaf(nr.w, v0, acc[3][0]); acc[3][1] = fmaf(nr.w, v1, acc[3][1]);
        acc[3][2] = fmaf(nr.w, v2, acc[3][2]); acc[3][3] = fmaf(nr.w, v3, acc[3][3]);
    }
#pragma unroll
    for (int h = 0; h < 4; h++) {
        float* orow = out + (size_t)h * NN * 128 + (size_t)node * 128;
#pragma unroll
        for (int j = 0; j < 4; j++) orow[j * 32 + lane] = acc[h][j];
    }
}

// ---------------- tf32 mma.sync GEMM with cp.async staging ----------------
// C[r*ldc + col0+c] = A_plane[M,K] @ Bt[*,K]^T ; raw fp32 staged, cvt at fragment read.
#define SSTR 20

__device__ __forceinline__ void mma_tf32(float c[4], const uint32_t a[4], const uint32_t b[2]) {
    asm volatile(
        "mma.sync.aligned.m16n8k8.row.col.f32.tf32.tf32.f32 "
        "{%0,%1,%2,%3}, {%4,%5,%6,%7}, {%8,%9}, {%0,%1,%2,%3};\n"
        : "+f"(c[0]), "+f"(c[1]), "+f"(c[2]), "+f"(c[3])
        : "r"(a[0]), "r"(a[1]), "r"(a[2]), "r"(a[3]), "r"(b[0]), "r"(b[1]));
}

__global__ __launch_bounds__(256, 2) void mma_gemm_k(const float* __restrict__ A,
                                                     const float* __restrict__ Bt,
                                                     float* __restrict__ C,
                                                     int M, int K, int ldc,
                                                     size_t aplane,
                                                     const float* __restrict__ bias,
                                                     int relu) {
    __shared__ uint32_t As[2][128 * SSTR];
    __shared__ uint32_t Bs[2][128 * SSTR];
    int tid = threadIdx.x, wid = tid >> 5, lane = tid & 31;
    int row0 = blockIdx.y * 128, col0 = blockIdx.x * 128;
    A += blockIdx.x * aplane;
    int lr = tid >> 2, lc = (tid & 3) * 4;
    int wm = wid & 1, wn = wid >> 1;
    int grp = lane >> 2, qid = lane & 3;
    int mw = wm * 64, nw = wn * 32;

    uint32_t asb = smem_u32(&As[0][0]);
    uint32_t bsb = smem_u32(&Bs[0][0]);

    float acc[4][4][4];
#pragma unroll
    for (int i = 0; i < 4; i++)
#pragma unroll
        for (int j = 0; j < 4; j++)
#pragma unroll
            for (int r = 0; r < 4; r++) acc[i][j][r] = 0.0f;

    auto prefetch = [&](int t, int b) {
        int k0 = t * 16;
        int gm0 = row0 + lr, gm1 = gm0 + 64;
        uint32_t off0 = (uint32_t)(b * 128 * SSTR + lr * SSTR + lc) * 4u;
        uint32_t off1 = off0 + 64u * SSTR * 4u;
        cpa16(asb + off0, A + (size_t)gm0 * K + k0 + lc, gm0 < M);
        cpa16(asb + off1, A + (size_t)gm1 * K + k0 + lc, gm1 < M);
        cpa16(bsb + off0, Bt + (size_t)(col0 + lr) * K + k0 + lc, true);
        cpa16(bsb + off1, Bt + (size_t)(col0 + lr + 64) * K + k0 + lc, true);
        asm volatile("cp.async.commit_group;" ::: "memory");
    };

    auto compute = [&](int b) {
        const uint32_t* as = As[b];
        const uint32_t* bs = Bs[b];
#pragma unroll
        for (int ks = 0; ks < 16; ks += 8) {
            uint32_t af[4][4], bf[4][2];
#pragma unroll
            for (int mf = 0; mf < 4; mf++) {
                int r = mw + mf * 16 + grp;
                af[mf][0] = tf32r(__uint_as_float(as[r * SSTR + ks + qid]));
                af[mf][1] = tf32r(__uint_as_float(as[(r + 8) * SSTR + ks + qid]));
                af[mf][2] = tf32r(__uint_as_float(as[r * SSTR + ks + qid + 4]));
                af[mf][3] = tf32r(__uint_as_float(as[(r + 8) * SSTR + ks + qid + 4]));
            }
#pragma unroll
            for (int nf = 0; nf < 4; nf++) {
                int cn = nw + nf * 8 + grp;
                bf[nf][0] = tf32r(__uint_as_float(bs[cn * SSTR + ks + qid]));
                bf[nf][1] = tf32r(__uint_as_float(bs[cn * SSTR + ks + qid + 4]));
            }
#pragma unroll
            for (int mf = 0; mf < 4; mf++)
#pragma unroll
                for (int nf = 0; nf < 4; nf++)
                    mma_tf32(acc[mf][nf], af[mf], bf[nf]);
        }
    };

    int ntiles = K >> 4;
    prefetch(0, 0);
    for (int t = 0; t < ntiles; t++) {
        __syncthreads();                       // all warps done reading buf (t+1)&1 (tile t-1)
        if (t + 1 < ntiles) {
            prefetch(t + 1, (t + 1) & 1);
            asm volatile("cp.async.wait_group 1;" ::: "memory");   // tile t complete
        } else {
            asm volatile("cp.async.wait_group 0;" ::: "memory");
        }
        __syncthreads();                       // copies visible block-wide
        compute(t & 1);
    }

    // epilogue (optional bias + relu)
#pragma unroll
    for (int mf = 0; mf < 4; mf++) {
        int r0 = row0 + mw + mf * 16 + grp;
        int r1 = r0 + 8;
#pragma unroll
        for (int nf = 0; nf < 4; nf++) {
            int cc = col0 + nw + nf * 8 + 2 * qid;
            float2 v0 = make_float2(acc[mf][nf][0], acc[mf][nf][1]);
            float2 v1 = make_float2(acc[mf][nf][2], acc[mf][nf][3]);
            if (bias) {
                float2 bb = *reinterpret_cast<const float2*>(bias + cc);
                v0.x += bb.x; v0.y += bb.y;
                v1.x += bb.x; v1.y += bb.y;
            }
            if (relu) {
                v0.x = fmaxf(v0.x, 0.f); v0.y = fmaxf(v0.y, 0.f);
                v1.x = fmaxf(v1.x, 0.f); v1.y = fmaxf(v1.y, 0.f);
            }
            if (r0 < M) *reinterpret_cast<float2*>(C + (size_t)r0 * ldc + cc) = v0;
            if (r1 < M) *reinterpret_cast<float2*>(C + (size_t)r1 * ldc + cc) = v1;
        }
    }
}

// ---------------- uniform-norm aggregation, 1 warp/node, strided lanes ----------------
template <int DIM, bool RELU>
__global__ __launch_bounds__(256) void agg_uni_k(const float* __restrict__ h,
                                                 float* __restrict__ out,
                                                 const float* __restrict__ bias) {
    int node = (blockIdx.x * blockDim.x + threadIdx.x) >> 5;
    if (node >= NN) return;
    int lane = threadIdx.x & 31;
    constexpr int V = DIM / 32;
    float acc[V];
    float d0 = g_dis[node];
    float sn = d0 * d0;
    const float* hr = h + (size_t)node * DIM;
#pragma unroll
    for (int j = 0; j < V; j++) acc[j] = sn * hr[j * 32 + lane];
    int beg = g_rowptr[node], end = g_rowptr[node + 1];
    for (int e = beg; e < end; e++) {
        int s = g_srcs[e];
        float nw = g_norm0[e];
        const float* hs = h + (size_t)s * DIM;
#pragma unroll
        for (int j = 0; j < V; j++)
            acc[j] = fmaf(nw, hs[j * 32 + lane], acc[j]);
    }
    float* orow = out + (size_t)node * DIM;
#pragma unroll
    for (int j = 0; j < V; j++) {
        float v = acc[j] + bias[j * 32 + lane];
        if (RELU) v = (v > 0.0f) ? v : 0.0f;
        orow[j * 32 + lane] = v;
    }
}

// ---------------- pooling: batch sorted -> run-length accumulate + rare atomics ----------------
__global__ void pool_k(const float* __restrict__ h, const int* __restrict__ batch) {
    int d = threadIdx.x;
    int i0 = blockIdx.x * 128;
    if (i0 >= NN) return;
    int i1 = i0 + 128; if (i1 > NN) i1 = NN;
    int cur = batch[i0];
    float s = 0.0f, m = -3.4e38f;
    int c = 0;
    for (int i = i0; i < i1; i++) {
        int g = batch[i];
        if (g != cur) {
            atomicAdd(&g_psum[cur * DD + d], s);
            atomicMax(&g_pmax[cur * DD + d], encf(m));
            if (d == 0) atomicAdd(&g_pcnt[cur], c);
            cur = g; s = 0.0f; m = -3.4e38f; c = 0;
        }
        float v = h[(size_t)i * DD + d];
        s += v;
        m = fmaxf(m, v);
        c++;
    }
    atomicAdd(&g_psum[cur * DD + d], s);
    atomicMax(&g_pmax[cur * DD + d], encf(m));
    if (d == 0) atomicAdd(&g_pcnt[cur], c);
}

// ---------------- final MLP ----------------
__global__ void final_k(const float* __restrict__ Wm1, const float* __restrict__ bm1,
                        const float* __restrict__ Wm2, const float* __restrict__ bm2,
                        float* __restrict__ out) {
    __shared__ float feat[256];
    __shared__ float z[8];
    int g = blockIdx.x, t = threadIdx.x;
    int cnt = g_pcnt[g];
    if (t < 128) {
        feat[t] = g_psum[g * DD + t] / fmaxf((float)cnt, 1.0f);
    } else {
        float m = decf(g_pmax[g * DD + (t - 128)]);
        feat[t] = (cnt > 0) ? m : 0.0f;
    }
    __syncthreads();
    int w = t >> 5, lane = t & 31;
    float s = 0.0f;
#pragma unroll
    for (int u = 0; u < 8; u++) {
        int k = lane + 32 * u;
        s = fmaf(feat[k], Wm1[k * 8 + w], s);
    }
#pragma unroll
    for (int off = 16; off > 0; off >>= 1)
        s += __shfl_down_sync(0xFFFFFFFFu, s, off);
    if (lane == 0) {
        float v = s + bm1[w];
        z[w] = (v > 0.0f) ? v : 0.0f;
    }
    __syncthreads();
    if (t < 2) {
        float o = bm2[t];
#pragma unroll
        for (int j = 0; j < 8; j++) o = fmaf(z[j], Wm2[j * 2 + t], o);
        out[g * 2 + t] = o;
    }
}

// ---------------- host launch ----------------
extern "C" void kernel_launch(void* const* d_in, const int* in_sizes, int n_in,
                              void* d_out, int out_size) {
    const float* x    = (const float*)d_in[0];
    const int*   ei   = (const int*)d_in[1];
    const float* attr = (const float*)d_in[2];
    const int*   batch= (const int*)d_in[3];
    const float* W1A  = (const float*)d_in[4];
    const float* b1A  = (const float*)d_in[5];
    const float* W1B  = (const float*)d_in[6];
    const float* b1B  = (const float*)d_in[7];
    const float* W1C  = (const float*)d_in[8];
    const float* b1C  = (const float*)d_in[9];
    const float* W1D  = (const float*)d_in[10];
    const float* b1D  = (const float*)d_in[11];
    const float* W2   = (const float*)d_in[12];
    const float* b2   = (const float*)d_in[13];
    const float* W3   = (const float*)d_in[14];
    const float* b3   = (const float*)d_in[15];
    const float* Wm1  = (const float*)d_in[16];
    const float* bm1  = (const float*)d_in[17];
    const float* Wm2  = (const float*)d_in[18];
    const float* bm2  = (const float*)d_in[19];
    float* out = (float*)d_out;

    float *bufA, *bufB, *Wt1, *Wt2, *Wt3, *bcat;
    cudaGetSymbolAddress((void**)&bufA, g_bufA);
    cudaGetSymbolAddress((void**)&bufB, g_bufB);
    cudaGetSymbolAddress((void**)&Wt1, g_Wt1);
    cudaGetSymbolAddress((void**)&Wt2, g_Wt2);
    cudaGetSymbolAddress((void**)&Wt3, g_Wt3);
    cudaGetSymbolAddress((void**)&bcat, g_bcat);

    zero_all_k<<<(5 * NN + 255) / 256, 256>>>();
    degree_k<<<(NE + 255) / 256, 256>>>(ei, attr);
    finalize_dis_k<<<(5 * NN + 255) / 256, 256>>>();
    scan1_k<<<49, 1024>>>();
    scan2_k<<<1, 64>>>();
    scan3_k<<<49, 1024>>>();
    scatter_k<<<(NE + 255) / 256, 256>>>(ei, attr);
    pack1_k<<<(512 * 128 + 255) / 256, 256>>>(W1A, W1B, W1C, W1D, b1A, b1B, b1C, b1D);
    pack2_k<<<(256 * 512 + 255) / 256, 256>>>(W2);
    pack3_k<<<(128 * 256 + 255) / 256, 256>>>(W3);

    // LAYER 1: aggregate x once (4 heads fused, 1 warp/node) -> bufA planes [4][NN,128]
    aggx_k<<<(NN * 32 + 255) / 256, 256>>>(x, bufA);
    // 4 per-head GEMMs [NN,128]@[128,128] + bias + relu -> bufB [NN,512] concat layout
    {
        dim3 grid(4, (NN + 127) / 128);
        mma_gemm_k<<<grid, 256>>>(bufA, Wt1, bufB, NN, 128, 512,
                                  (size_t)NN * 128, bcat, 1);
    }
    // LAYER 2: GEMM [NN,512]@[512,256] -> bufA, then agg+bias+relu -> bufB
    {
        dim3 grid(2, (NN + 127) / 128);
        mma_gemm_k<<<grid, 256>>>(bufB, Wt2, bufA, NN, 512, 256, 0, nullptr, 0);
    }
    agg_uni_k<256, true><<<(NN * 32 + 255) / 256, 256>>>(bufA, bufB, b2);
    // LAYER 3: GEMM [NN,256]@[256,128] -> bufA, then agg+bias -> bufB
    {
        dim3 grid(1, (NN + 127) / 128);
        mma_gemm_k<<<grid, 256>>>(bufB, Wt3, bufA, NN, 256, 128, 0, nullptr, 0);
    }
    agg_uni_k<128, false><<<(NN * 32 + 255) / 256, 256>>>(bufA, bufB, b3);
    pool_k<<<(NN + 127) / 128, 128>>>(bufB, batch);
    final_k<<<NG, 256>>>(Wm1, bm1, Wm2, bm2, out);
}

// round 10
// speedup vs baseline: 1.3694x; 1.3694x over previous
#include <cuda_runtime.h>
#include <cuda_bf16.h>
#include <cstdint>

#define NN 50000
#define NE 600000
#define DD 128
#define NG 64

// ---------------- scratch (device globals; no allocation allowed) ----------------
__device__ float    g_dis[5 * NN];          // plane 0: unweighted, 1..4: per-head (deg -> rsqrt)
__device__ int      g_cnt[NN];
__device__ int      g_fill[NN];
__device__ int      g_rowptr[NN + 1];
__device__ int      g_bsum[64];
__device__ int      g_srcs[NE];
__device__ float    g_norm0[NE];
__device__ float    g_norm4[4 * NE];
__device__ float    g_Wt1[512 * 128];       // Wcat^T  [N=512][K=128], tf32-rounded
__device__ float    g_Wt2[256 * 512];       // W2^T    [N=256][K=512], tf32-rounded
__device__ float    g_Wt3[128 * 256];       // W3^T    [N=128][K=256], tf32-rounded
__device__ float    g_bcat[512];
__device__ float    g_bufA[(size_t)NN * 512];
__device__ float    g_bufB[(size_t)NN * 512];
__device__ float    g_psum[NG * DD];
__device__ unsigned g_pmax[NG * DD];
__device__ int      g_pcnt[NG];

// ---------------- helpers ----------------
__device__ __forceinline__ unsigned encf(float f) {
    unsigned b = __float_as_uint(f);
    return (b & 0x80000000u) ? ~b : (b | 0x80000000u);
}
__device__ __forceinline__ float decf(unsigned u) {
    unsigned b = (u & 0x80000000u) ? (u & 0x7FFFFFFFu) : ~u;
    return __uint_as_float(b);
}
__device__ __forceinline__ float tf32f(float f) {      // round fp32 -> tf32-valued fp32
    uint32_t u;
    asm("cvt.rna.tf32.f32 %0, %1;" : "=r"(u) : "f"(f));
    return __uint_as_float(u);
}

// ---------------- zero scratch ----------------
__global__ void zero_all_k() {
    int i = blockIdx.x * blockDim.x + threadIdx.x;
    if (i < 5 * NN) g_dis[i] = 0.0f;
    if (i < NN) { g_cnt[i] = 0; g_fill[i] = 0; }
    if (i < NG * DD) { g_psum[i] = 0.0f; g_pmax[i] = 0u; }
    if (i < NG) g_pcnt[i] = 0;
}

// ---------------- degree + count (plane0 derived from g_cnt later) ----------------
__global__ void degree_k(const int* __restrict__ ei, const float* __restrict__ attr) {
    int e = blockIdx.x * blockDim.x + threadIdx.x;
    if (e >= NE) return;
    int dst = ei[NE + e];
    float4 a = *reinterpret_cast<const float4*>(attr + e * 4);
    atomicAdd(&g_cnt[dst], 1);
    atomicAdd(&g_dis[1 * NN + dst], a.x);
    atomicAdd(&g_dis[2 * NN + dst], a.y);
    atomicAdd(&g_dis[3 * NN + dst], a.z);
    atomicAdd(&g_dis[4 * NN + dst], a.w);
}

__global__ void finalize_dis_k() {
    int i = blockIdx.x * blockDim.x + threadIdx.x;
    if (i >= 5 * NN) return;
    if (i < NN)
        g_dis[i] = rsqrtf((float)g_cnt[i] + 1.0f);        // unweighted: cnt + self loop
    else
        g_dis[i] = rsqrtf(g_dis[i] + 1.0f);               // weighted: +1 self loop
}

// ---------------- 3-phase multi-block scan over 50000 counts ----------------
__global__ void scan1_k() {
    __shared__ int ws[32];
    int b = blockIdx.x, t = threadIdx.x, lane = t & 31, w = t >> 5;
    int i = b * 1024 + t;
    int v = (i < NN) ? g_cnt[i] : 0;
    int inc = v;
#pragma unroll
    for (int off = 1; off < 32; off <<= 1) {
        int x = __shfl_up_sync(0xFFFFFFFFu, inc, off);
        if (lane >= off) inc += x;
    }
    if (lane == 31) ws[w] = inc;
    __syncthreads();
    if (w == 0) {
        int s = ws[lane];
#pragma unroll
        for (int off = 1; off < 32; off <<= 1) {
            int x = __shfl_up_sync(0xFFFFFFFFu, s, off);
            if (lane >= off) s += x;
        }
        ws[lane] = s;
    }
    __syncthreads();
    int pre = (w > 0) ? ws[w - 1] : 0;
    int incl = pre + inc;
    if (i < NN) g_rowptr[i + 1] = incl;
    if (t == 1023) g_bsum[b] = incl;
}
__global__ void scan2_k() {
    __shared__ int s[64];
    int t = threadIdx.x;
    int v = (t < 49) ? g_bsum[t] : 0;
    s[t] = v; __syncthreads();
    for (int off = 1; off < 64; off <<= 1) {
        int x = (t >= off) ? s[t - off] : 0;
        __syncthreads();
        s[t] += x;
        __syncthreads();
    }
    if (t < 49) g_bsum[t] = s[t] - v;   // exclusive
}
__global__ void scan3_k() {
    int b = blockIdx.x, t = threadIdx.x, i = b * 1024 + t;
    if (i < NN) g_rowptr[i + 1] += g_bsum[b];
    if (i == 0) g_rowptr[0] = 0;
}

// ---------------- scatter edges into CSR, precompute norms ----------------
__global__ void scatter_k(const int* __restrict__ ei, const float* __restrict__ attr) {
    int e = blockIdx.x * blockDim.x + threadIdx.x;
    if (e >= NE) return;
    int src = ei[e];
    int dst = ei[NE + e];
    float4 a = *reinterpret_cast<const float4*>(attr + e * 4);
    int pos = g_rowptr[dst] + atomicAdd(&g_fill[dst], 1);
    g_srcs[pos] = src;
    g_norm0[pos] = g_dis[src] * g_dis[dst];
    float4 nv;
    nv.x = g_dis[1 * NN + src] * a.x * g_dis[1 * NN + dst];
    nv.y = g_dis[2 * NN + src] * a.y * g_dis[2 * NN + dst];
    nv.z = g_dis[3 * NN + src] * a.z * g_dis[3 * NN + dst];
    nv.w = g_dis[4 * NN + src] * a.w * g_dis[4 * NN + dst];
    *reinterpret_cast<float4*>(g_norm4 + pos * 4) = nv;
}

// ---------------- weight transposes (tf32 pre-rounded) ----------------
__global__ void pack1_k(const float* __restrict__ WA, const float* __restrict__ WB,
                        const float* __restrict__ WC, const float* __restrict__ WD,
                        const float* __restrict__ bA, const float* __restrict__ bB,
                        const float* __restrict__ bC, const float* __restrict__ bD) {
    int idx = blockIdx.x * blockDim.x + threadIdx.x;   // [0, 512*128)
    if (idx >= 512 * 128) return;
    int k = idx & 127, n = idx >> 7;
    int h = n >> 7, c = n & 127;
    const float* W = (h == 0) ? WA : (h == 1) ? WB : (h == 2) ? WC : WD;
    g_Wt1[idx] = tf32f(W[k * 128 + c]);
    if (k == 0) {
        const float* b = (h == 0) ? bA : (h == 1) ? bB : (h == 2) ? bC : bD;
        g_bcat[n] = b[c];
    }
}
__global__ void pack2_k(const float* __restrict__ W2) {
    int idx = blockIdx.x * blockDim.x + threadIdx.x;   // [0, 256*512)
    if (idx >= 256 * 512) return;
    int k = idx & 511, n = idx >> 9;
    g_Wt2[idx] = tf32f(W2[k * 256 + n]);
}
__global__ void pack3_k(const float* __restrict__ W3) {
    int idx = blockIdx.x * blockDim.x + threadIdx.x;   // [0, 128*256)
    if (idx >= 128 * 256) return;
    int k = idx & 255, n = idx >> 8;
    g_Wt3[idx] = tf32f(W3[k * 128 + n]);
}

// ---------------- fused 4-head aggregation of x (1 warp/node), tf32-rounded output ----------------
// out planes: out[h*NN*128 + node*128 + c]
__global__ __launch_bounds__(256) void aggx_k(const float* __restrict__ x,
                                              float* __restrict__ out) {
    int node = (blockIdx.x * blockDim.x + threadIdx.x) >> 5;
    if (node >= NN) return;
    int lane = threadIdx.x & 31;
    float sn[4];
#pragma unroll
    for (int h = 0; h < 4; h++) {
        float d = g_dis[(h + 1) * NN + node];
        sn[h] = d * d;                       // self-loop norm = 1/deg_w
    }
    const float* xr = x + (size_t)node * 128;
    float acc[4][4];
#pragma unroll
    for (int j = 0; j < 4; j++) {
        float v = xr[j * 32 + lane];
#pragma unroll
        for (int h = 0; h < 4; h++) acc[h][j] = sn[h] * v;
    }
    int beg = g_rowptr[node], end = g_rowptr[node + 1];
    for (int e = beg; e < end; e++) {
        int s = g_srcs[e];
        float4 nr = *reinterpret_cast<const float4*>(g_norm4 + (size_t)e * 4);
        const float* xs = x + (size_t)s * 128;
        float v0 = xs[lane], v1 = xs[32 + lane], v2 = xs[64 + lane], v3 = xs[96 + lane];
        acc[0][0] = fmaf(nr.x, v0, acc[0][0]); acc[0][1] = fmaf(nr.x, v1, acc[0][1]);
        acc[0][2] = fmaf(nr.x, v2, acc[0][2]); acc[0][3] = fmaf(nr.x, v3, acc[0][3]);
        acc[1][0] = fmaf(nr.y, v0, acc[1][0]); acc[1][1] = fmaf(nr.y, v1, acc[1][1]);
        acc[1][2] = fmaf(nr.y, v2, acc[1][2]); acc[1][3] = fmaf(nr.y, v3, acc[1][3]);
        acc[2][0] = fmaf(nr.z, v0, acc[2][0]); acc[2][1] = fmaf(nr.z, v1, acc[2][1]);
        acc[2][2] = fmaf(nr.z, v2, acc[2][2]); acc[2][3] = fmaf(nr.z, v3, acc[2][3]);
        acc[3][0] = fmaf(nr.w, v0, acc[3][0]); acc[3][1] = fmaf(nr.w, v1, acc[3][1]);
        acc[3][2] = fmaf(nr.w, v2, acc[3][2]); acc[3][3] = fmaf(nr.w, v3, acc[3][3]);
    }
#pragma unroll
    for (int h = 0; h < 4; h++) {
        float* orow = out + (size_t)h * NN * 128 + (size_t)node * 128;
#pragma unroll
        for (int j = 0; j < 4; j++) orow[j * 32 + lane] = tf32f(acc[h][j]);
    }
}

// ---------------- tf32 mma.sync GEMM (register staging, inputs pre-rounded) ----------------
// C[r*ldc + col0+c] = A_plane[M,K] @ Bt[*,K]^T
// block tile 128x128, warp tile 64x32 (warp grid 2x4), K-tile 16, double-buffered.
// SMEM stride 20 words: bank sets {20n%32} disjoint -> frag LDS conflict-free.
#define SSTR 20

__device__ __forceinline__ void mma_tf32(float c[4], const uint32_t a[4], const uint32_t b[2]) {
    asm volatile(
        "mma.sync.aligned.m16n8k8.row.col.f32.tf32.tf32.f32 "
        "{%0,%1,%2,%3}, {%4,%5,%6,%7}, {%8,%9}, {%0,%1,%2,%3};\n"
        : "+f"(c[0]), "+f"(c[1]), "+f"(c[2]), "+f"(c[3])
        : "r"(a[0]), "r"(a[1]), "r"(a[2]), "r"(a[3]), "r"(b[0]), "r"(b[1]));
}

__global__ __launch_bounds__(256, 2) void mma_gemm_k(const float* __restrict__ A,
                                                     const float* __restrict__ Bt,
                                                     float* __restrict__ C,
                                                     int M, int K, int ldc,
                                                     size_t aplane,
                                                     const float* __restrict__ bias,
                                                     int relu, int cvtout) {
    __shared__ uint32_t As[2][128 * SSTR];
    __shared__ uint32_t Bs[2][128 * SSTR];
    int tid = threadIdx.x, wid = tid >> 5, lane = tid & 31;
    int row0 = blockIdx.y * 128, col0 = blockIdx.x * 128;
    A += blockIdx.x * aplane;
    int lr = tid >> 2, lc = (tid & 3) * 4;
    int wm = wid & 1, wn = wid >> 1;
    int grp = lane >> 2, qid = lane & 3;
    int mw = wm * 64, nw = wn * 32;

    float acc[4][4][4];
#pragma unroll
    for (int i = 0; i < 4; i++)
#pragma unroll
        for (int j = 0; j < 4; j++)
#pragma unroll
            for (int r = 0; r < 4; r++) acc[i][j][r] = 0.0f;

    uint4 av0, av1, bv0, bv1;
    const uint4 z4 = make_uint4(0u, 0u, 0u, 0u);

    auto gload = [&](int t) {
        int k0 = t * 16;
        int gm0 = row0 + lr, gm1 = row0 + lr + 64;
        av0 = (gm0 < M) ? *reinterpret_cast<const uint4*>(A + (size_t)gm0 * K + k0 + lc) : z4;
        av1 = (gm1 < M) ? *reinterpret_cast<const uint4*>(A + (size_t)gm1 * K + k0 + lc) : z4;
        bv0 = *reinterpret_cast<const uint4*>(Bt + (size_t)(col0 + lr) * K + k0 + lc);
        bv1 = *reinterpret_cast<const uint4*>(Bt + (size_t)(col0 + lr + 64) * K + k0 + lc);
    };
    auto sstore = [&](int b) {
        *reinterpret_cast<uint4*>(&As[b][lr * SSTR + lc]) = av0;
        *reinterpret_cast<uint4*>(&As[b][(lr + 64) * SSTR + lc]) = av1;
        *reinterpret_cast<uint4*>(&Bs[b][lr * SSTR + lc]) = bv0;
        *reinterpret_cast<uint4*>(&Bs[b][(lr + 64) * SSTR + lc]) = bv1;
    };
    auto compute = [&](int b) {
        const uint32_t* as = As[b];
        const uint32_t* bs = Bs[b];
#pragma unroll
        for (int ks = 0; ks < 16; ks += 8) {
            uint32_t af[4][4], bf[4][2];
#pragma unroll
            for (int mf = 0; mf < 4; mf++) {
                int r = mw + mf * 16 + grp;
                af[mf][0] = as[r * SSTR + ks + qid];
                af[mf][1] = as[(r + 8) * SSTR + ks + qid];
                af[mf][2] = as[r * SSTR + ks + qid + 4];
                af[mf][3] = as[(r + 8) * SSTR + ks + qid + 4];
            }
#pragma unroll
            for (int nf = 0; nf < 4; nf++) {
                int cn = nw + nf * 8 + grp;
                bf[nf][0] = bs[cn * SSTR + ks + qid];
                bf[nf][1] = bs[cn * SSTR + ks + qid + 4];
            }
#pragma unroll
            for (int mf = 0; mf < 4; mf++)
#pragma unroll
                for (int nf = 0; nf < 4; nf++)
                    mma_tf32(acc[mf][nf], af[mf], bf[nf]);
        }
    };

    int ntiles = K >> 4;
    gload(0);
    sstore(0);
    __syncthreads();
    for (int t = 0; t < ntiles; t++) {
        if (t + 1 < ntiles) gload(t + 1);
        compute(t & 1);
        if (t + 1 < ntiles) {
            sstore((t + 1) & 1);
            __syncthreads();
        }
    }

    // epilogue (optional bias + relu + tf32 output rounding for GEMM-consumed buffers)
#pragma unroll
    for (int mf = 0; mf < 4; mf++) {
        int r0 = row0 + mw + mf * 16 + grp;
        int r1 = r0 + 8;
#pragma unroll
        for (int nf = 0; nf < 4; nf++) {
            int cc = col0 + nw + nf * 8 + 2 * qid;
            float2 v0 = make_float2(acc[mf][nf][0], acc[mf][nf][1]);
            float2 v1 = make_float2(acc[mf][nf][2], acc[mf][nf][3]);
            if (bias) {
                float2 bb = *reinterpret_cast<const float2*>(bias + cc);
                v0.x += bb.x; v0.y += bb.y;
                v1.x += bb.x; v1.y += bb.y;
            }
            if (relu) {
                v0.x = fmaxf(v0.x, 0.f); v0.y = fmaxf(v0.y, 0.f);
                v1.x = fmaxf(v1.x, 0.f); v1.y = fmaxf(v1.y, 0.f);
            }
            if (cvtout) {
                v0.x = tf32f(v0.x); v0.y = tf32f(v0.y);
                v1.x = tf32f(v1.x); v1.y = tf32f(v1.y);
            }
            if (r0 < M) *reinterpret_cast<float2*>(C + (size_t)r0 * ldc + cc) = v0;
            if (r1 < M) *reinterpret_cast<float2*>(C + (size_t)r1 * ldc + cc) = v1;
        }
    }
}

// ---------------- uniform-norm aggregation, 1 warp/node, optional tf32-rounded output ----------------
template <int DIM, bool RELU, bool TF32OUT>
__global__ __launch_bounds__(256) void agg_uni_k(const float* __restrict__ h,
                                                 float* __restrict__ out,
                                                 const float* __restrict__ bias) {
    int node = (blockIdx.x * blockDim.x + threadIdx.x) >> 5;
    if (node >= NN) return;
    int lane = threadIdx.x & 31;
    constexpr int V = DIM / 32;
    float acc[V];
    float d0 = g_dis[node];
    float sn = d0 * d0;
    const float* hr = h + (size_t)node * DIM;
#pragma unroll
    for (int j = 0; j < V; j++) acc[j] = sn * hr[j * 32 + lane];
    int beg = g_rowptr[node], end = g_rowptr[node + 1];
    for (int e = beg; e < end; e++) {
        int s = g_srcs[e];
        float nw = g_norm0[e];
        const float* hs = h + (size_t)s * DIM;
#pragma unroll
        for (int j = 0; j < V; j++)
            acc[j] = fmaf(nw, hs[j * 32 + lane], acc[j]);
    }
    float* orow = out + (size_t)node * DIM;
#pragma unroll
    for (int j = 0; j < V; j++) {
        float v = acc[j] + bias[j * 32 + lane];
        if (RELU) v = (v > 0.0f) ? v : 0.0f;
        if (TF32OUT) v = tf32f(v);
        orow[j * 32 + lane] = v;
    }
}

// ---------------- pooling: batch sorted -> run-length accumulate + rare atomics ----------------
__global__ void pool_k(const float* __restrict__ h, const int* __restrict__ batch) {
    int d = threadIdx.x;
    int i0 = blockIdx.x * 128;
    if (i0 >= NN) return;
    int i1 = i0 + 128; if (i1 > NN) i1 = NN;
    int cur = batch[i0];
    float s = 0.0f, m = -3.4e38f;
    int c = 0;
    for (int i = i0; i < i1; i++) {
        int g = batch[i];
        if (g != cur) {
            atomicAdd(&g_psum[cur * DD + d], s);
            atomicMax(&g_pmax[cur * DD + d], encf(m));
            if (d == 0) atomicAdd(&g_pcnt[cur], c);
            cur = g; s = 0.0f; m = -3.4e38f; c = 0;
        }
        float v = h[(size_t)i * DD + d];
        s += v;
        m = fmaxf(m, v);
        c++;
    }
    atomicAdd(&g_psum[cur * DD + d], s);
    atomicMax(&g_pmax[cur * DD + d], encf(m));
    if (d == 0) atomicAdd(&g_pcnt[cur], c);
}

// ---------------- final MLP ----------------
__global__ void final_k(const float* __restrict__ Wm1, const float* __restrict__ bm1,
                        const float* __restrict__ Wm2, const float* __restrict__ bm2,
                        float* __restrict__ out) {
    __shared__ float feat[256];
    __shared__ float z[8];
    int g = blockIdx.x, t = threadIdx.x;
    int cnt = g_pcnt[g];
    if (t < 128) {
        feat[t] = g_psum[g * DD + t] / fmaxf((float)cnt, 1.0f);
    } else {
        float m = decf(g_pmax[g * DD + (t - 128)]);
        feat[t] = (cnt > 0) ? m : 0.0f;
    }
    __syncthreads();
    int w = t >> 5, lane = t & 31;
    float s = 0.0f;
#pragma unroll
    for (int u = 0; u < 8; u++) {
        int k = lane + 32 * u;
        s = fmaf(feat[k], Wm1[k * 8 + w], s);
    }
#pragma unroll
    for (int off = 16; off > 0; off >>= 1)
        s += __shfl_down_sync(0xFFFFFFFFu, s, off);
    if (lane == 0) {
        float v = s + bm1[w];
        z[w] = (v > 0.0f) ? v : 0.0f;
    }
    __syncthreads();
    if (t < 2) {
        float o = bm2[t];
#pragma unroll
        for (int j = 0; j < 8; j++) o = fmaf(z[j], Wm2[j * 2 + t], o);
        out[g * 2 + t] = o;
    }
}

// ---------------- host launch ----------------
extern "C" void kernel_launch(void* const* d_in, const int* in_sizes, int n_in,
                              void* d_out, int out_size) {
    const float* x    = (const float*)d_in[0];
    const int*   ei   = (const int*)d_in[1];
    const float* attr = (const float*)d_in[2];
    const int*   batch= (const int*)d_in[3];
    const float* W1A  = (const float*)d_in[4];
    const float* b1A  = (const float*)d_in[5];
    const float* W1B  = (const float*)d_in[6];
    const float* b1B  = (const float*)d_in[7];
    const float* W1C  = (const float*)d_in[8];
    const float* b1C  = (const float*)d_in[9];
    const float* W1D  = (const float*)d_in[10];
    const float* b1D  = (const float*)d_in[11];
    const float* W2   = (const float*)d_in[12];
    const float* b2   = (const float*)d_in[13];
    const float* W3   = (const float*)d_in[14];
    const float* b3   = (const float*)d_in[15];
    const float* Wm1  = (const float*)d_in[16];
    const float* bm1  = (const float*)d_in[17];
    const float* Wm2  = (const float*)d_in[18];
    const float* bm2  = (const float*)d_in[19];
    float* out = (float*)d_out;

    float *bufA, *bufB, *Wt1, *Wt2, *Wt3, *bcat;
    cudaGetSymbolAddress((void**)&bufA, g_bufA);
    cudaGetSymbolAddress((void**)&bufB, g_bufB);
    cudaGetSymbolAddress((void**)&Wt1, g_Wt1);
    cudaGetSymbolAddress((void**)&Wt2, g_Wt2);
    cudaGetSymbolAddress((void**)&Wt3, g_Wt3);
    cudaGetSymbolAddress((void**)&bcat, g_bcat);

    zero_all_k<<<(5 * NN + 255) / 256, 256>>>();
    degree_k<<<(NE + 255) / 256, 256>>>(ei, attr);
    finalize_dis_k<<<(5 * NN + 255) / 256, 256>>>();
    scan1_k<<<49, 1024>>>();
    scan2_k<<<1, 64>>>();
    scan3_k<<<49, 1024>>>();
    scatter_k<<<(NE + 255) / 256, 256>>>(ei, attr);
    pack1_k<<<(512 * 128 + 255) / 256, 256>>>(W1A, W1B, W1C, W1D, b1A, b1B, b1C, b1D);
    pack2_k<<<(256 * 512 + 255) / 256, 256>>>(W2);
    pack3_k<<<(128 * 256 + 255) / 256, 256>>>(W3);

    // LAYER 1: aggregate x once (4 heads fused, tf32-rounded out) -> bufA planes [4][NN,128]
    aggx_k<<<(NN * 32 + 255) / 256, 256>>>(x, bufA);
    // 4 per-head GEMMs [NN,128]@[128,128] + bias + relu + tf32 out -> bufB [NN,512] concat
    {
        dim3 grid(4, (NN + 127) / 128);
        mma_gemm_k<<<grid, 256>>>(bufA, Wt1, bufB, NN, 128, 512,
                                  (size_t)NN * 128, bcat, 1, 1);
    }
    // LAYER 2: GEMM [NN,512]@[512,256] -> bufA (fp32), agg+bias+relu+tf32 out -> bufB
    {
        dim3 grid(2, (NN + 127) / 128);
        mma_gemm_k<<<grid, 256>>>(bufB, Wt2, bufA, NN, 512, 256, 0, nullptr, 0, 0);
    }
    agg_uni_k<256, true, true><<<(NN * 32 + 255) / 256, 256>>>(bufA, bufB, b2);
    // LAYER 3: GEMM [NN,256]@[256,128] -> bufA (fp32), agg+bias -> bufB
    {
        dim3 grid(1, (NN + 127) / 128);
        mma_gemm_k<<<grid, 256>>>(bufB, Wt3, bufA, NN, 256, 128, 0, nullptr, 0, 0);
    }
    agg_uni_k<128, false, false><<<(NN * 32 + 255) / 256, 256>>>(bufA, bufB, b3);
    pool_k<<<(NN + 127) / 128, 128>>>(bufB, batch);
    final_k<<<NG, 256>>>(Wm1, bm1, Wm2, bm2, out);
}

// round 11
// speedup vs baseline: 1.4052x; 1.0261x over previous
#include <cuda_runtime.h>
#include <cuda_bf16.h>
#include <cstdint>

#define NN 50000
#define NE 600000
#define DD 128
#define NG 64

// ---------------- scratch (device globals; no allocation allowed) ----------------
__device__ float    g_dis[5 * NN];          // plane 0: unweighted, 1..4: per-head (deg -> rsqrt)
__device__ int      g_cnt[NN];
__device__ int      g_fill[NN];
__device__ int      g_rowptr[NN + 1];
__device__ int      g_aggr[64];
__device__ int      g_flag[64];
__device__ int      g_srcs[NE];
__device__ float    g_norm0[NE];
__device__ float    g_norm4[4 * NE];
__device__ float    g_Wt1[512 * 128];       // Wcat^T  [N=512][K=128] (head h = rows h*128..)
__device__ float    g_Wt2[256 * 512];       // W2^T    [N=256][K=512]
__device__ float    g_Wt3[128 * 256];       // W3^T    [N=128][K=256]
__device__ float    g_bcat[512];
__device__ float    g_bufA[(size_t)NN * 512];
__device__ float    g_bufB[(size_t)NN * 512];
__device__ float    g_psum[NG * DD];
__device__ unsigned g_pmax[NG * DD];
__device__ int      g_pcnt[NG];

// ---------------- helpers ----------------
__device__ __forceinline__ unsigned encf(float f) {
    unsigned b = __float_as_uint(f);
    return (b & 0x80000000u) ? ~b : (b | 0x80000000u);
}
__device__ __forceinline__ float decf(unsigned u) {
    unsigned b = (u & 0x80000000u) ? (u & 0x7FFFFFFFu) : ~u;
    return __uint_as_float(b);
}
__device__ __forceinline__ uint32_t tf32r(float f) {
    uint32_t u;
    asm("cvt.rna.tf32.f32 %0, %1;" : "=r"(u) : "f"(f));
    return u;
}

// ---------------- zero scratch ----------------
__global__ void zero_all_k() {
    int i = blockIdx.x * blockDim.x + threadIdx.x;
    if (i < 5 * NN) g_dis[i] = 0.0f;
    if (i < NN) { g_cnt[i] = 0; g_fill[i] = 0; }
    if (i < NG * DD) { g_psum[i] = 0.0f; g_pmax[i] = 0u; }
    if (i < NG) { g_pcnt[i] = 0; g_flag[i] = 0; }
}

// ---------------- degree + count (plane0 derived from g_cnt later) ----------------
__global__ void degree_k(const int* __restrict__ ei, const float* __restrict__ attr) {
    int e = blockIdx.x * blockDim.x + threadIdx.x;
    if (e >= NE) return;
    int dst = ei[NE + e];
    float4 a = *reinterpret_cast<const float4*>(attr + e * 4);
    atomicAdd(&g_cnt[dst], 1);
    atomicAdd(&g_dis[1 * NN + dst], a.x);
    atomicAdd(&g_dis[2 * NN + dst], a.y);
    atomicAdd(&g_dis[3 * NN + dst], a.z);
    atomicAdd(&g_dis[4 * NN + dst], a.w);
}

// ---------------- fused finalize + single-kernel decoupled-lookback scan ----------------
// 49 blocks x 1024 threads; all blocks co-resident (49 <= 148 SMs) -> lookback is safe.
__global__ __launch_bounds__(1024) void scan_k() {
    int b = blockIdx.x, t = threadIdx.x, lane = t & 31, w = t >> 5;
    int gi = b * 1024 + t;

    // folded finalize_dis: 250k entries over 50176 threads
#pragma unroll
    for (int c = 0; c < 5; c++) {
        int i = gi + c * 50176;
        if (i < 5 * NN) {
            if (i < NN) g_dis[i] = rsqrtf((float)g_cnt[i] + 1.0f);   // unweighted: cnt + self loop
            else        g_dis[i] = rsqrtf(g_dis[i] + 1.0f);          // weighted: +1 self loop
        }
    }

    // local inclusive scan of this block's 1024 counts
    __shared__ int ws[32];
    __shared__ int carry_sh;
    int v = (gi < NN) ? g_cnt[gi] : 0;
    int inc = v;
#pragma unroll
    for (int off = 1; off < 32; off <<= 1) {
        int x = __shfl_up_sync(0xFFFFFFFFu, inc, off);
        if (lane >= off) inc += x;
    }
    if (lane == 31) ws[w] = inc;
    __syncthreads();
    if (w == 0) {
        int s = ws[lane];
#pragma unroll
        for (int off = 1; off < 32; off <<= 1) {
            int x = __shfl_up_sync(0xFFFFFFFFu, s, off);
            if (lane >= off) s += x;
        }
        ws[lane] = s;
    }
    if (t == 0) carry_sh = 0;
    __syncthreads();
    int pre = (w > 0) ? ws[w - 1] : 0;
    int incl = pre + inc;

    // publish this block's aggregate (total = ws[31])
    if (t == 1023) {
        g_aggr[b] = incl;
        __threadfence();
        atomicExch(&g_flag[b], 1);
    }
    // lookback: thread t (< b) sums predecessor aggregates
    if (t < b) {
        while (atomicAdd(&g_flag[t], 0) == 0) { }
        atomicAdd(&carry_sh, g_aggr[t]);
    }
    __syncthreads();
    int carry = carry_sh;
    if (gi < NN) g_rowptr[gi + 1] = carry + incl;
    if (gi == 0) g_rowptr[0] = 0;
}

// ---------------- scatter edges into CSR, precompute norms ----------------
__global__ void scatter_k(const int* __restrict__ ei, const float* __restrict__ attr) {
    int e = blockIdx.x * blockDim.x + threadIdx.x;
    if (e >= NE) return;
    int src = ei[e];
    int dst = ei[NE + e];
    float4 a = *reinterpret_cast<const float4*>(attr + e * 4);
    int pos = g_rowptr[dst] + atomicAdd(&g_fill[dst], 1);
    g_srcs[pos] = src;
    g_norm0[pos] = g_dis[src] * g_dis[dst];
    float4 nv;
    nv.x = g_dis[1 * NN + src] * a.x * g_dis[1 * NN + dst];
    nv.y = g_dis[2 * NN + src] * a.y * g_dis[2 * NN + dst];
    nv.z = g_dis[3 * NN + src] * a.z * g_dis[3 * NN + dst];
    nv.w = g_dis[4 * NN + src] * a.w * g_dis[4 * NN + dst];
    *reinterpret_cast<float4*>(g_norm4 + pos * 4) = nv;
}

// ---------------- single fused weight-transpose kernel ----------------
__global__ void pack_k(const float* __restrict__ WA, const float* __restrict__ WB,
                       const float* __restrict__ WC, const float* __restrict__ WD,
                       const float* __restrict__ bA, const float* __restrict__ bB,
                       const float* __restrict__ bC, const float* __restrict__ bD,
                       const float* __restrict__ W2, const float* __restrict__ W3) {
    int idx = blockIdx.x * blockDim.x + threadIdx.x;
    if (idx < 512 * 128) {                               // Wt1
        int k = idx & 127, n = idx >> 7;
        int h = n >> 7, c = n & 127;
        const float* W = (h == 0) ? WA : (h == 1) ? WB : (h == 2) ? WC : WD;
        g_Wt1[idx] = W[k * 128 + c];
        if (k == 0) {
            const float* b = (h == 0) ? bA : (h == 1) ? bB : (h == 2) ? bC : bD;
            g_bcat[n] = b[c];
        }
    } else if (idx < 512 * 128 + 256 * 512) {            // Wt2
        int j = idx - 512 * 128;
        int k = j & 511, n = j >> 9;
        g_Wt2[j] = W2[k * 256 + n];
    } else if (idx < 512 * 128 + 256 * 512 + 128 * 256) {// Wt3
        int j = idx - (512 * 128 + 256 * 512);
        int k = j & 255, n = j >> 8;
        g_Wt3[j] = W3[k * 128 + n];
    }
}

// ---------------- fused 4-head aggregation of x (1 warp/node, 128 cols) ----------------
// out planes: out[h*NN*128 + node*128 + c]
__global__ __launch_bounds__(256) void aggx_k(const float* __restrict__ x,
                                              float* __restrict__ out) {
    int node = (blockIdx.x * blockDim.x + threadIdx.x) >> 5;
    if (node >= NN) return;
    int lane = threadIdx.x & 31;
    float sn[4];
#pragma unroll
    for (int h = 0; h < 4; h++) {
        float d = g_dis[(h + 1) * NN + node];
        sn[h] = d * d;                       // self-loop norm = 1/deg_w
    }
    const float* xr = x + (size_t)node * 128;
    float acc[4][4];
#pragma unroll
    for (int j = 0; j < 4; j++) {
        float v = xr[j * 32 + lane];
#pragma unroll
        for (int h = 0; h < 4; h++) acc[h][j] = sn[h] * v;
    }
    int beg = g_rowptr[node], end = g_rowptr[node + 1];
    for (int e = beg; e < end; e++) {
        int s = g_srcs[e];
        float4 nr = *reinterpret_cast<const float4*>(g_norm4 + (size_t)e * 4);
        const float* xs = x + (size_t)s * 128;
        float v0 = xs[lane], v1 = xs[32 + lane], v2 = xs[64 + lane], v3 = xs[96 + lane];
        acc[0][0] = fmaf(nr.x, v0, acc[0][0]); acc[0][1] = fmaf(nr.x, v1, acc[0][1]);
        acc[0][2] = fmaf(nr.x, v2, acc[0][2]); acc[0][3] = fmaf(nr.x, v3, acc[0][3]);
        acc[1][0] = fmaf(nr.y, v0, acc[1][0]); acc[1][1] = fmaf(nr.y, v1, acc[1][1]);
        acc[1][2] = fmaf(nr.y, v2, acc[1][2]); acc[1][3] = fmaf(nr.y, v3, acc[1][3]);
        acc[2][0] = fmaf(nr.z, v0, acc[2][0]); acc[2][1] = fmaf(nr.z, v1, acc[2][1]);
        acc[2][2] = fmaf(nr.z, v2, acc[2][2]); acc[2][3] = fmaf(nr.z, v3, acc[2][3]);
        acc[3][0] = fmaf(nr.w, v0, acc[3][0]); acc[3][1] = fmaf(nr.w, v1, acc[3][1]);
        acc[3][2] = fmaf(nr.w, v2, acc[3][2]); acc[3][3] = fmaf(nr.w, v3, acc[3][3]);
    }
#pragma unroll
    for (int h = 0; h < 4; h++) {
        float* orow = out + (size_t)h * NN * 128 + (size_t)node * 128;
#pragma unroll
        for (int j = 0; j < 4; j++) orow[j * 32 + lane] = acc[h][j];
    }
}

// ---------------- tf32 mma.sync GEMM (register staging, cvt at staging) ----------------
// C[r*ldc + col0+c] = A_plane[M,K] @ Bt[*,K]^T
// block tile 128x128, warp tile 64x32 (warp grid 2x4), K-tile 16, double-buffered.
// SMEM stride 20 words: bank sets {20n%32} disjoint -> frag LDS conflict-free.
#define SSTR 20

__device__ __forceinline__ void mma_tf32(float c[4], const uint32_t a[4], const uint32_t b[2]) {
    asm volatile(
        "mma.sync.aligned.m16n8k8.row.col.f32.tf32.tf32.f32 "
        "{%0,%1,%2,%3}, {%4,%5,%6,%7}, {%8,%9}, {%0,%1,%2,%3};\n"
        : "+f"(c[0]), "+f"(c[1]), "+f"(c[2]), "+f"(c[3])
        : "r"(a[0]), "r"(a[1]), "r"(a[2]), "r"(a[3]), "r"(b[0]), "r"(b[1]));
}

__global__ __launch_bounds__(256, 2) void mma_gemm_k(const float* __restrict__ A,
                                                     const float* __restrict__ Bt,
                                                     float* __restrict__ C,
                                                     int M, int K, int ldc,
                                                     size_t aplane,
                                                     const float* __restrict__ bias,
                                                     int relu) {
    __shared__ uint32_t As[2][128 * SSTR];
    __shared__ uint32_t Bs[2][128 * SSTR];
    int tid = threadIdx.x, wid = tid >> 5, lane = tid & 31;
    int row0 = blockIdx.y * 128, col0 = blockIdx.x * 128;
    A += blockIdx.x * aplane;
    int lr = tid >> 2, lc = (tid & 3) * 4;
    int wm = wid & 1, wn = wid >> 1;
    int grp = lane >> 2, qid = lane & 3;
    int mw = wm * 64, nw = wn * 32;

    float acc[4][4][4];
#pragma unroll
    for (int i = 0; i < 4; i++)
#pragma unroll
        for (int j = 0; j < 4; j++)
#pragma unroll
            for (int r = 0; r < 4; r++) acc[i][j][r] = 0.0f;

    float4 av0, av1, bv0, bv1;
    const float4 z4 = make_float4(0.f, 0.f, 0.f, 0.f);

    auto gload = [&](int t) {
        int k0 = t * 16;
        int gm0 = row0 + lr, gm1 = row0 + lr + 64;
        av0 = (gm0 < M) ? *reinterpret_cast<const float4*>(A + (size_t)gm0 * K + k0 + lc) : z4;
        av1 = (gm1 < M) ? *reinterpret_cast<const float4*>(A + (size_t)gm1 * K + k0 + lc) : z4;
        bv0 = *reinterpret_cast<const float4*>(Bt + (size_t)(col0 + lr) * K + k0 + lc);
        bv1 = *reinterpret_cast<const float4*>(Bt + (size_t)(col0 + lr + 64) * K + k0 + lc);
    };
    auto sstore = [&](int b) {
        uint4 u;
        u.x = tf32r(av0.x); u.y = tf32r(av0.y); u.z = tf32r(av0.z); u.w = tf32r(av0.w);
        *reinterpret_cast<uint4*>(&As[b][lr * SSTR + lc]) = u;
        u.x = tf32r(av1.x); u.y = tf32r(av1.y); u.z = tf32r(av1.z); u.w = tf32r(av1.w);
        *reinterpret_cast<uint4*>(&As[b][(lr + 64) * SSTR + lc]) = u;
        u.x = tf32r(bv0.x); u.y = tf32r(bv0.y); u.z = tf32r(bv0.z); u.w = tf32r(bv0.w);
        *reinterpret_cast<uint4*>(&Bs[b][lr * SSTR + lc]) = u;
        u.x = tf32r(bv1.x); u.y = tf32r(bv1.y); u.z = tf32r(bv1.z); u.w = tf32r(bv1.w);
        *reinterpret_cast<uint4*>(&Bs[b][(lr + 64) * SSTR + lc]) = u;
    };
    auto compute = [&](int b) {
        const uint32_t* as = As[b];
        const uint32_t* bs = Bs[b];
#pragma unroll
        for (int ks = 0; ks < 16; ks += 8) {
            uint32_t af[4][4], bf[4][2];
#pragma unroll
            for (int mf = 0; mf < 4; mf++) {
                int r = mw + mf * 16 + grp;
                af[mf][0] = as[r * SSTR + ks + qid];
                af[mf][1] = as[(r + 8) * SSTR + ks + qid];
                af[mf][2] = as[r * SSTR + ks + qid + 4];
                af[mf][3] = as[(r + 8) * SSTR + ks + qid + 4];
            }
#pragma unroll
            for (int nf = 0; nf < 4; nf++) {
                int cn = nw + nf * 8 + grp;
                bf[nf][0] = bs[cn * SSTR + ks + qid];
                bf[nf][1] = bs[cn * SSTR + ks + qid + 4];
            }
#pragma unroll
            for (int mf = 0; mf < 4; mf++)
#pragma unroll
                for (int nf = 0; nf < 4; nf++)
                    mma_tf32(acc[mf][nf], af[mf], bf[nf]);
        }
    };

    int ntiles = K >> 4;
    gload(0);
    sstore(0);
    __syncthreads();
    for (int t = 0; t < ntiles; t++) {
        if (t + 1 < ntiles) gload(t + 1);
        compute(t & 1);
        if (t + 1 < ntiles) {
            sstore((t + 1) & 1);
            __syncthreads();
        }
    }

    // epilogue (optional bias + relu)
#pragma unroll
    for (int mf = 0; mf < 4; mf++) {
        int r0 = row0 + mw + mf * 16 + grp;
        int r1 = r0 + 8;
#pragma unroll
        for (int nf = 0; nf < 4; nf++) {
            int cc = col0 + nw + nf * 8 + 2 * qid;
            float2 v0 = make_float2(acc[mf][nf][0], acc[mf][nf][1]);
            float2 v1 = make_float2(acc[mf][nf][2], acc[mf][nf][3]);
            if (bias) {
                float2 bb = *reinterpret_cast<const float2*>(bias + cc);
                v0.x += bb.x; v0.y += bb.y;
                v1.x += bb.x; v1.y += bb.y;
            }
            if (relu) {
                v0.x = fmaxf(v0.x, 0.f); v0.y = fmaxf(v0.y, 0.f);
                v1.x = fmaxf(v1.x, 0.f); v1.y = fmaxf(v1.y, 0.f);
            }
            if (r0 < M) *reinterpret_cast<float2*>(C + (size_t)r0 * ldc + cc) = v0;
            if (r1 < M) *reinterpret_cast<float2*>(C + (size_t)r1 * ldc + cc) = v1;
        }
    }
}

// ---------------- uniform-norm aggregation, 1 warp/node, strided lanes ----------------
template <int DIM, bool RELU>
__global__ __launch_bounds__(256) void agg_uni_k(const float* __restrict__ h,
                                                 float* __restrict__ out,
                                                 const float* __restrict__ bias) {
    int node = (blockIdx.x * blockDim.x + threadIdx.x) >> 5;
    if (node >= NN) return;
    int lane = threadIdx.x & 31;
    constexpr int V = DIM / 32;
    float acc[V];
    float d0 = g_dis[node];
    float sn = d0 * d0;
    const float* hr = h + (size_t)node * DIM;
#pragma unroll
    for (int j = 0; j < V; j++) acc[j] = sn * hr[j * 32 + lane];
    int beg = g_rowptr[node], end = g_rowptr[node + 1];
    for (int e = beg; e < end; e++) {
        int s = g_srcs[e];
        float nw = g_norm0[e];
        const float* hs = h + (size_t)s * DIM;
#pragma unroll
        for (int j = 0; j < V; j++)
            acc[j] = fmaf(nw, hs[j * 32 + lane], acc[j]);
    }
    float* orow = out + (size_t)node * DIM;
#pragma unroll
    for (int j = 0; j < V; j++) {
        float v = acc[j] + bias[j * 32 + lane];
        if (RELU) v = (v > 0.0f) ? v : 0.0f;
        orow[j * 32 + lane] = v;
    }
}

// ---------------- pooling: batch sorted -> run-length accumulate + rare atomics ----------------
__global__ void pool_k(const float* __restrict__ h, const int* __restrict__ batch) {
    int d = threadIdx.x;
    int i0 = blockIdx.x * 128;
    if (i0 >= NN) return;
    int i1 = i0 + 128; if (i1 > NN) i1 = NN;
    int cur = batch[i0];
    float s = 0.0f, m = -3.4e38f;
    int c = 0;
    for (int i = i0; i < i1; i++) {
        int g = batch[i];
        if (g != cur) {
            atomicAdd(&g_psum[cur * DD + d], s);
            atomicMax(&g_pmax[cur * DD + d], encf(m));
            if (d == 0) atomicAdd(&g_pcnt[cur], c);
            cur = g; s = 0.0f; m = -3.4e38f; c = 0;
        }
        float v = h[(size_t)i * DD + d];
        s += v;
        m = fmaxf(m, v);
        c++;
    }
    atomicAdd(&g_psum[cur * DD + d], s);
    atomicMax(&g_pmax[cur * DD + d], encf(m));
    if (d == 0) atomicAdd(&g_pcnt[cur], c);
}

// ---------------- final MLP ----------------
__global__ void final_k(const float* __restrict__ Wm1, const float* __restrict__ bm1,
                        const float* __restrict__ Wm2, const float* __restrict__ bm2,
                        float* __restrict__ out) {
    __shared__ float feat[256];
    __shared__ float z[8];
    int g = blockIdx.x, t = threadIdx.x;
    int cnt = g_pcnt[g];
    if (t < 128) {
        feat[t] = g_psum[g * DD + t] / fmaxf((float)cnt, 1.0f);
    } else {
        float m = decf(g_pmax[g * DD + (t - 128)]);
        feat[t] = (cnt > 0) ? m : 0.0f;
    }
    __syncthreads();
    int w = t >> 5, lane = t & 31;
    float s = 0.0f;
#pragma unroll
    for (int u = 0; u < 8; u++) {
        int k = lane + 32 * u;
        s = fmaf(feat[k], Wm1[k * 8 + w], s);
    }
#pragma unroll
    for (int off = 16; off > 0; off >>= 1)
        s += __shfl_down_sync(0xFFFFFFFFu, s, off);
    if (lane == 0) {
        float v = s + bm1[w];
        z[w] = (v > 0.0f) ? v : 0.0f;
    }
    __syncthreads();
    if (t < 2) {
        float o = bm2[t];
#pragma unroll
        for (int j = 0; j < 8; j++) o = fmaf(z[j], Wm2[j * 2 + t], o);
        out[g * 2 + t] = o;
    }
}

// ---------------- host launch ----------------
extern "C" void kernel_launch(void* const* d_in, const int* in_sizes, int n_in,
                              void* d_out, int out_size) {
    const float* x    = (const float*)d_in[0];
    const int*   ei   = (const int*)d_in[1];
    const float* attr = (const float*)d_in[2];
    const int*   batch= (const int*)d_in[3];
    const float* W1A  = (const float*)d_in[4];
    const float* b1A  = (const float*)d_in[5];
    const float* W1B  = (const float*)d_in[6];
    const float* b1B  = (const float*)d_in[7];
    const float* W1C  = (const float*)d_in[8];
    const float* b1C  = (const float*)d_in[9];
    const float* W1D  = (const float*)d_in[10];
    const float* b1D  = (const float*)d_in[11];
    const float* W2   = (const float*)d_in[12];
    const float* b2   = (const float*)d_in[13];
    const float* W3   = (const float*)d_in[14];
    const float* b3   = (const float*)d_in[15];
    const float* Wm1  = (const float*)d_in[16];
    const float* bm1  = (const float*)d_in[17];
    const float* Wm2  = (const float*)d_in[18];
    const float* bm2  = (const float*)d_in[19];
    float* out = (float*)d_out;

    float *bufA, *bufB, *Wt1, *Wt2, *Wt3, *bcat;
    cudaGetSymbolAddress((void**)&bufA, g_bufA);
    cudaGetSymbolAddress((void**)&bufB, g_bufB);
    cudaGetSymbolAddress((void**)&Wt1, g_Wt1);
    cudaGetSymbolAddress((void**)&Wt2, g_Wt2);
    cudaGetSymbolAddress((void**)&Wt3, g_Wt3);
    cudaGetSymbolAddress((void**)&bcat, g_bcat);

    zero_all_k<<<(5 * NN + 255) / 256, 256>>>();
    degree_k<<<(NE + 255) / 256, 256>>>(ei, attr);
    scan_k<<<49, 1024>>>();                                      // finalize + scan fused
    scatter_k<<<(NE + 255) / 256, 256>>>(ei, attr);
    pack_k<<<(512 * 128 + 256 * 512 + 128 * 256 + 255) / 256, 256>>>(
        W1A, W1B, W1C, W1D, b1A, b1B, b1C, b1D, W2, W3);

    // LAYER 1: aggregate x once (4 heads fused, 1 warp/node) -> bufA planes [4][NN,128]
    aggx_k<<<(NN * 32 + 255) / 256, 256>>>(x, bufA);
    // 4 per-head GEMMs [NN,128]@[128,128] + bias + relu -> bufB [NN,512] concat layout
    {
        dim3 grid(4, (NN + 127) / 128);
        mma_gemm_k<<<grid, 256>>>(bufA, Wt1, bufB, NN, 128, 512,
                                  (size_t)NN * 128, bcat, 1);
    }
    // LAYER 2: GEMM [NN,512]@[512,256] -> bufA, then agg+bias+relu -> bufB
    {
        dim3 grid(2, (NN + 127) / 128);
        mma_gemm_k<<<grid, 256>>>(bufB, Wt2, bufA, NN, 512, 256, 0, nullptr, 0);
    }
    agg_uni_k<256, true><<<(NN * 32 + 255) / 256, 256>>>(bufA, bufB, b2);
    // LAYER 3: GEMM [NN,256]@[256,128] -> bufA, then agg+bias -> bufB
    {
        dim3 grid(1, (NN + 127) / 128);
        mma_gemm_k<<<grid, 256>>>(bufB, Wt3, bufA, NN, 256, 128, 0, nullptr, 0);
    }
    agg_uni_k<128, false><<<(NN * 32 + 255) / 256, 256>>>(bufA, bufB, b3);
    pool_k<<<(NN + 127) / 128, 128>>>(bufB, batch);
    final_k<<<NG, 256>>>(Wm1, bm1, Wm2, bm2, out);
}

// round 12
// speedup vs baseline: 1.4588x; 1.0381x over previous
#include <cuda_runtime.h>
#include <cuda_bf16.h>
#include <cstdint>

#define NN 50000
#define NE 600000
#define DD 128
#define NG 64

// ---------------- scratch (device globals; no allocation allowed) ----------------
__device__ float    g_disA[(size_t)NN * 8];  // AoS: [node][0]=unweighted, [1..4]=heads, [5..7] pad
__device__ int      g_cnt[NN];
__device__ int      g_fill[NN];
__device__ int      g_rowptr[NN + 1];
__device__ int      g_aggr[64];
__device__ int      g_flag[64];
__device__ int      g_srcs[NE];
__device__ float    g_norm0[NE];
__device__ float    g_norm4[4 * NE];
__device__ float    g_Wt1[512 * 128];       // Wcat^T  [N=512][K=128] (head h = rows h*128..)
__device__ float    g_Wt2[256 * 512];       // W2^T    [N=256][K=512]
__device__ float    g_Wt3[128 * 256];       // W3^T    [N=128][K=256]
__device__ float    g_bcat[512];
__device__ float    g_bufA[(size_t)NN * 512];
__device__ float    g_bufB[(size_t)NN * 512];
__device__ float    g_psum[NG * DD];
__device__ unsigned g_pmax[NG * DD];
__device__ int      g_pcnt[NG];

// ---------------- helpers ----------------
__device__ __forceinline__ unsigned encf(float f) {
    unsigned b = __float_as_uint(f);
    return (b & 0x80000000u) ? ~b : (b | 0x80000000u);
}
__device__ __forceinline__ float decf(unsigned u) {
    unsigned b = (u & 0x80000000u) ? (u & 0x7FFFFFFFu) : ~u;
    return __uint_as_float(b);
}
__device__ __forceinline__ uint32_t tf32r(float f) {
    uint32_t u;
    asm("cvt.rna.tf32.f32 %0, %1;" : "=r"(u) : "f"(f));
    return u;
}

// ---------------- zero scratch ----------------
__global__ void zero_all_k() {
    int i = blockIdx.x * blockDim.x + threadIdx.x;
    if (i < 8 * NN) g_disA[i] = 0.0f;
    if (i < NN) { g_cnt[i] = 0; g_fill[i] = 0; }
    if (i < NG * DD) { g_psum[i] = 0.0f; g_pmax[i] = 0u; }
    if (i < NG) { g_pcnt[i] = 0; g_flag[i] = 0; }
}

// ---------------- degree + count; AoS atomics (one 32B sector per edge-dst) ----------------
__global__ void degree_k(const int* __restrict__ ei, const float* __restrict__ attr) {
    int e = blockIdx.x * blockDim.x + threadIdx.x;
    if (e >= NE) return;
    int dst = ei[NE + e];
    float4 a = *reinterpret_cast<const float4*>(attr + e * 4);
    float* row = g_disA + (size_t)dst * 8;
    atomicAdd(&g_cnt[dst], 1);
    atomicAdd(row + 1, a.x);
    atomicAdd(row + 2, a.y);
    atomicAdd(row + 3, a.z);
    atomicAdd(row + 4, a.w);
}

// ---------------- fused finalize + single-kernel decoupled-lookback scan ----------------
// 49 blocks x 1024 threads; all blocks co-resident (49 <= 148 SMs) -> lookback is safe.
__global__ __launch_bounds__(1024) void scan_k() {
    int b = blockIdx.x, t = threadIdx.x, lane = t & 31, w = t >> 5;
    int gi = b * 1024 + t;

    int v = 0;
    if (gi < NN) {
        v = g_cnt[gi];
        float* row = g_disA + (size_t)gi * 8;
        row[0] = rsqrtf((float)v + 1.0f);          // unweighted: cnt + self loop
#pragma unroll
        for (int h = 1; h <= 4; h++)
            row[h] = rsqrtf(row[h] + 1.0f);        // weighted: +1 self loop
    }

    // local inclusive scan of this block's 1024 counts
    __shared__ int ws[32];
    __shared__ int carry_sh;
    int inc = v;
#pragma unroll
    for (int off = 1; off < 32; off <<= 1) {
        int x = __shfl_up_sync(0xFFFFFFFFu, inc, off);
        if (lane >= off) inc += x;
    }
    if (lane == 31) ws[w] = inc;
    __syncthreads();
    if (w == 0) {
        int s = ws[lane];
#pragma unroll
        for (int off = 1; off < 32; off <<= 1) {
            int x = __shfl_up_sync(0xFFFFFFFFu, s, off);
            if (lane >= off) s += x;
        }
        ws[lane] = s;
    }
    if (t == 0) carry_sh = 0;
    __syncthreads();
    int pre = (w > 0) ? ws[w - 1] : 0;
    int incl = pre + inc;

    // publish this block's aggregate
    if (t == 1023) {
        g_aggr[b] = incl;
        __threadfence();
        atomicExch(&g_flag[b], 1);
    }
    // lookback: thread t (< b) sums predecessor aggregates
    if (t < b) {
        while (atomicAdd(&g_flag[t], 0) == 0) { }
        atomicAdd(&carry_sh, g_aggr[t]);
    }
    __syncthreads();
    int carry = carry_sh;
    if (gi < NN) g_rowptr[gi + 1] = carry + incl;
    if (gi == 0) g_rowptr[0] = 0;
}

// ---------------- scatter edges into CSR; AoS dis reads (2 sectors per edge) ----------------
__global__ void scatter_k(const int* __restrict__ ei, const float* __restrict__ attr) {
    int e = blockIdx.x * blockDim.x + threadIdx.x;
    if (e >= NE) return;
    int src = ei[e];
    int dst = ei[NE + e];
    float4 a = *reinterpret_cast<const float4*>(attr + e * 4);
    const float* sr = g_disA + (size_t)src * 8;
    const float* dr = g_disA + (size_t)dst * 8;
    float4 s03 = *reinterpret_cast<const float4*>(sr);   // [0..3]
    float  s4  = sr[4];
    float4 d03 = *reinterpret_cast<const float4*>(dr);
    float  d4  = dr[4];
    int pos = g_rowptr[dst] + atomicAdd(&g_fill[dst], 1);
    g_srcs[pos] = src;
    g_norm0[pos] = s03.x * d03.x;
    float4 nv;
    nv.x = s03.y * a.x * d03.y;
    nv.y = s03.z * a.y * d03.z;
    nv.z = s03.w * a.z * d03.w;
    nv.w = s4    * a.w * d4;
    *reinterpret_cast<float4*>(g_norm4 + pos * 4) = nv;
}

// ---------------- single fused weight-transpose kernel ----------------
__global__ void pack_k(const float* __restrict__ WA, const float* __restrict__ WB,
                       const float* __restrict__ WC, const float* __restrict__ WD,
                       const float* __restrict__ bA, const float* __restrict__ bB,
                       const float* __restrict__ bC, const float* __restrict__ bD,
                       const float* __restrict__ W2, const float* __restrict__ W3) {
    int idx = blockIdx.x * blockDim.x + threadIdx.x;
    if (idx < 512 * 128) {                               // Wt1
        int k = idx & 127, n = idx >> 7;
        int h = n >> 7, c = n & 127;
        const float* W = (h == 0) ? WA : (h == 1) ? WB : (h == 2) ? WC : WD;
        g_Wt1[idx] = W[k * 128 + c];
        if (k == 0) {
            const float* b = (h == 0) ? bA : (h == 1) ? bB : (h == 2) ? bC : bD;
            g_bcat[n] = b[c];
        }
    } else if (idx < 512 * 128 + 256 * 512) {            // Wt2
        int j = idx - 512 * 128;
        int k = j & 511, n = j >> 9;
        g_Wt2[j] = W2[k * 256 + n];
    } else if (idx < 512 * 128 + 256 * 512 + 128 * 256) {// Wt3
        int j = idx - (512 * 128 + 256 * 512);
        int k = j & 255, n = j >> 8;
        g_Wt3[j] = W3[k * 128 + n];
    }
}

// ---------------- fused 4-head aggregation of x (1 warp/node, 128 cols) ----------------
// out planes: out[h*NN*128 + node*128 + c]
__global__ __launch_bounds__(256) void aggx_k(const float* __restrict__ x,
                                              float* __restrict__ out) {
    int node = (blockIdx.x * blockDim.x + threadIdx.x) >> 5;
    if (node >= NN) return;
    int lane = threadIdx.x & 31;
    const float* drow = g_disA + (size_t)node * 8;
    float sn[4];
#pragma unroll
    for (int h = 0; h < 4; h++) {
        float d = drow[h + 1];
        sn[h] = d * d;                       // self-loop norm = 1/deg_w
    }
    const float* xr = x + (size_t)node * 128;
    float acc[4][4];
#pragma unroll
    for (int j = 0; j < 4; j++) {
        float v = xr[j * 32 + lane];
#pragma unroll
        for (int h = 0; h < 4; h++) acc[h][j] = sn[h] * v;
    }
    int beg = g_rowptr[node], end = g_rowptr[node + 1];
    for (int e = beg; e < end; e++) {
        int s = g_srcs[e];
        float4 nr = *reinterpret_cast<const float4*>(g_norm4 + (size_t)e * 4);
        const float* xs = x + (size_t)s * 128;
        float v0 = xs[lane], v1 = xs[32 + lane], v2 = xs[64 + lane], v3 = xs[96 + lane];
        acc[0][0] = fmaf(nr.x, v0, acc[0][0]); acc[0][1] = fmaf(nr.x, v1, acc[0][1]);
        acc[0][2] = fmaf(nr.x, v2, acc[0][2]); acc[0][3] = fmaf(nr.x, v3, acc[0][3]);
        acc[1][0] = fmaf(nr.y, v0, acc[1][0]); acc[1][1] = fmaf(nr.y, v1, acc[1][1]);
        acc[1][2] = fmaf(nr.y, v2, acc[1][2]); acc[1][3] = fmaf(nr.y, v3, acc[1][3]);
        acc[2][0] = fmaf(nr.z, v0, acc[2][0]); acc[2][1] = fmaf(nr.z, v1, acc[2][1]);
        acc[2][2] = fmaf(nr.z, v2, acc[2][2]); acc[2][3] = fmaf(nr.z, v3, acc[2][3]);
        acc[3][0] = fmaf(nr.w, v0, acc[3][0]); acc[3][1] = fmaf(nr.w, v1, acc[3][1]);
        acc[3][2] = fmaf(nr.w, v2, acc[3][2]); acc[3][3] = fmaf(nr.w, v3, acc[3][3]);
    }
#pragma unroll
    for (int h = 0; h < 4; h++) {
        float* orow = out + (size_t)h * NN * 128 + (size_t)node * 128;
#pragma unroll
        for (int j = 0; j < 4; j++) orow[j * 32 + lane] = acc[h][j];
    }
}

// ---------------- tf32 mma.sync GEMM (register staging, cvt at staging) ----------------
// C[r*ldc + col0+c] = A_plane[M,K] @ Bt[*,K]^T
// block tile 128x128, warp tile 64x32 (warp grid 2x4), K-tile 16, double-buffered.
// SMEM stride 20 words: bank sets {20n%32} disjoint -> frag LDS conflict-free.
#define SSTR 20

__device__ __forceinline__ void mma_tf32(float c[4], const uint32_t a[4], const uint32_t b[2]) {
    asm volatile(
        "mma.sync.aligned.m16n8k8.row.col.f32.tf32.tf32.f32 "
        "{%0,%1,%2,%3}, {%4,%5,%6,%7}, {%8,%9}, {%0,%1,%2,%3};\n"
        : "+f"(c[0]), "+f"(c[1]), "+f"(c[2]), "+f"(c[3])
        : "r"(a[0]), "r"(a[1]), "r"(a[2]), "r"(a[3]), "r"(b[0]), "r"(b[1]));
}

__global__ __launch_bounds__(256, 2) void mma_gemm_k(const float* __restrict__ A,
                                                     const float* __restrict__ Bt,
                                                     float* __restrict__ C,
                                                     int M, int K, int ldc,
                                                     size_t aplane,
                                                     const float* __restrict__ bias,
                                                     int relu) {
    __shared__ uint32_t As[2][128 * SSTR];
    __shared__ uint32_t Bs[2][128 * SSTR];
    int tid = threadIdx.x, wid = tid >> 5, lane = tid & 31;
    int row0 = blockIdx.y * 128, col0 = blockIdx.x * 128;
    A += blockIdx.x * aplane;
    int lr = tid >> 2, lc = (tid & 3) * 4;
    int wm = wid & 1, wn = wid >> 1;
    int grp = lane >> 2, qid = lane & 3;
    int mw = wm * 64, nw = wn * 32;

    float acc[4][4][4];
#pragma unroll
    for (int i = 0; i < 4; i++)
#pragma unroll
        for (int j = 0; j < 4; j++)
#pragma unroll
            for (int r = 0; r < 4; r++) acc[i][j][r] = 0.0f;

    float4 av0, av1, bv0, bv1;
    const float4 z4 = make_float4(0.f, 0.f, 0.f, 0.f);

    auto gload = [&](int t) {
        int k0 = t * 16;
        int gm0 = row0 + lr, gm1 = row0 + lr + 64;
        av0 = (gm0 < M) ? *reinterpret_cast<const float4*>(A + (size_t)gm0 * K + k0 + lc) : z4;
        av1 = (gm1 < M) ? *reinterpret_cast<const float4*>(A + (size_t)gm1 * K + k0 + lc) : z4;
        bv0 = *reinterpret_cast<const float4*>(Bt + (size_t)(col0 + lr) * K + k0 + lc);
        bv1 = *reinterpret_cast<const float4*>(Bt + (size_t)(col0 + lr + 64) * K + k0 + lc);
    };
    auto sstore = [&](int b) {
        uint4 u;
        u.x = tf32r(av0.x); u.y = tf32r(av0.y); u.z = tf32r(av0.z); u.w = tf32r(av0.w);
        *reinterpret_cast<uint4*>(&As[b][lr * SSTR + lc]) = u;
        u.x = tf32r(av1.x); u.y = tf32r(av1.y); u.z = tf32r(av1.z); u.w = tf32r(av1.w);
        *reinterpret_cast<uint4*>(&As[b][(lr + 64) * SSTR + lc]) = u;
        u.x = tf32r(bv0.x); u.y = tf32r(bv0.y); u.z = tf32r(bv0.z); u.w = tf32r(bv0.w);
        *reinterpret_cast<uint4*>(&Bs[b][lr * SSTR + lc]) = u;
        u.x = tf32r(bv1.x); u.y = tf32r(bv1.y); u.z = tf32r(bv1.z); u.w = tf32r(bv1.w);
        *reinterpret_cast<uint4*>(&Bs[b][(lr + 64) * SSTR + lc]) = u;
    };
    auto compute = [&](int b) {
        const uint32_t* as = As[b];
        const uint32_t* bs = Bs[b];
#pragma unroll
        for (int ks = 0; ks < 16; ks += 8) {
            uint32_t af[4][4], bf[4][2];
#pragma unroll
            for (int mf = 0; mf < 4; mf++) {
                int r = mw + mf * 16 + grp;
                af[mf][0] = as[r * SSTR + ks + qid];
                af[mf][1] = as[(r + 8) * SSTR + ks + qid];
                af[mf][2] = as[r * SSTR + ks + qid + 4];
                af[mf][3] = as[(r + 8) * SSTR + ks + qid + 4];
            }
#pragma unroll
            for (int nf = 0; nf < 4; nf++) {
                int cn = nw + nf * 8 + grp;
                bf[nf][0] = bs[cn * SSTR + ks + qid];
                bf[nf][1] = bs[cn * SSTR + ks + qid + 4];
            }
#pragma unroll
            for (int mf = 0; mf < 4; mf++)
#pragma unroll
                for (int nf = 0; nf < 4; nf++)
                    mma_tf32(acc[mf][nf], af[mf], bf[nf]);
        }
    };

    int ntiles = K >> 4;
    gload(0);
    sstore(0);
    __syncthreads();
    for (int t = 0; t < ntiles; t++) {
        if (t + 1 < ntiles) gload(t + 1);
        compute(t & 1);
        if (t + 1 < ntiles) {
            sstore((t + 1) & 1);
            __syncthreads();
        }
    }

    // epilogue (optional bias + relu)
#pragma unroll
    for (int mf = 0; mf < 4; mf++) {
        int r0 = row0 + mw + mf * 16 + grp;
        int r1 = r0 + 8;
#pragma unroll
        for (int nf = 0; nf < 4; nf++) {
            int cc = col0 + nw + nf * 8 + 2 * qid;
            float2 v0 = make_float2(acc[mf][nf][0], acc[mf][nf][1]);
            float2 v1 = make_float2(acc[mf][nf][2], acc[mf][nf][3]);
            if (bias) {
                float2 bb = *reinterpret_cast<const float2*>(bias + cc);
                v0.x += bb.x; v0.y += bb.y;
                v1.x += bb.x; v1.y += bb.y;
            }
            if (relu) {
                v0.x = fmaxf(v0.x, 0.f); v0.y = fmaxf(v0.y, 0.f);
                v1.x = fmaxf(v1.x, 0.f); v1.y = fmaxf(v1.y, 0.f);
            }
            if (r0 < M) *reinterpret_cast<float2*>(C + (size_t)r0 * ldc + cc) = v0;
            if (r1 < M) *reinterpret_cast<float2*>(C + (size_t)r1 * ldc + cc) = v1;
        }
    }
}

// ---------------- uniform-norm aggregation, 1 warp/node, strided lanes ----------------
template <int DIM, bool RELU>
__global__ __launch_bounds__(256) void agg_uni_k(const float* __restrict__ h,
                                                 float* __restrict__ out,
                                                 const float* __restrict__ bias) {
    int node = (blockIdx.x * blockDim.x + threadIdx.x) >> 5;
    if (node >= NN) return;
    int lane = threadIdx.x & 31;
    constexpr int V = DIM / 32;
    float acc[V];
    float d0 = g_disA[(size_t)node * 8];
    float sn = d0 * d0;
    const float* hr = h + (size_t)node * DIM;
#pragma unroll
    for (int j = 0; j < V; j++) acc[j] = sn * hr[j * 32 + lane];
    int beg = g_rowptr[node], end = g_rowptr[node + 1];
    for (int e = beg; e < end; e++) {
        int s = g_srcs[e];
        float nw = g_norm0[e];
        const float* hs = h + (size_t)s * DIM;
#pragma unroll
        for (int j = 0; j < V; j++)
            acc[j] = fmaf(nw, hs[j * 32 + lane], acc[j]);
    }
    float* orow = out + (size_t)node * DIM;
#pragma unroll
    for (int j = 0; j < V; j++) {
        float v = acc[j] + bias[j * 32 + lane];
        if (RELU) v = (v > 0.0f) ? v : 0.0f;
        orow[j * 32 + lane] = v;
    }
}

// ---------------- pooling: batch sorted -> run-length accumulate + rare atomics ----------------
__global__ void pool_k(const float* __restrict__ h, const int* __restrict__ batch) {
    int d = threadIdx.x;
    int i0 = blockIdx.x * 128;
    if (i0 >= NN) return;
    int i1 = i0 + 128; if (i1 > NN) i1 = NN;
    int cur = batch[i0];
    float s = 0.0f, m = -3.4e38f;
    int c = 0;
    for (int i = i0; i < i1; i++) {
        int g = batch[i];
        if (g != cur) {
            atomicAdd(&g_psum[cur * DD + d], s);
            atomicMax(&g_pmax[cur * DD + d], encf(m));
            if (d == 0) atomicAdd(&g_pcnt[cur], c);
            cur = g; s = 0.0f; m = -3.4e38f; c = 0;
        }
        float v = h[(size_t)i * DD + d];
        s += v;
        m = fmaxf(m, v);
        c++;
    }
    atomicAdd(&g_psum[cur * DD + d], s);
    atomicMax(&g_pmax[cur * DD + d], encf(m));
    if (d == 0) atomicAdd(&g_pcnt[cur], c);
}

// ---------------- final MLP ----------------
__global__ void final_k(const float* __restrict__ Wm1, const float* __restrict__ bm1,
                        const float* __restrict__ Wm2, const float* __restrict__ bm2,
                        float* __restrict__ out) {
    __shared__ float feat[256];
    __shared__ float z[8];
    int g = blockIdx.x, t = threadIdx.x;
    int cnt = g_pcnt[g];
    if (t < 128) {
        feat[t] = g_psum[g * DD + t] / fmaxf((float)cnt, 1.0f);
    } else {
        float m = decf(g_pmax[g * DD + (t - 128)]);
        feat[t] = (cnt > 0) ? m : 0.0f;
    }
    __syncthreads();
    int w = t >> 5, lane = t & 31;
    float s = 0.0f;
#pragma unroll
    for (int u = 0; u < 8; u++) {
        int k = lane + 32 * u;
        s = fmaf(feat[k], Wm1[k * 8 + w], s);
    }
#pragma unroll
    for (int off = 16; off > 0; off >>= 1)
        s += __shfl_down_sync(0xFFFFFFFFu, s, off);
    if (lane == 0) {
        float v = s + bm1[w];
        z[w] = (v > 0.0f) ? v : 0.0f;
    }
    __syncthreads();
    if (t < 2) {
        float o = bm2[t];
#pragma unroll
        for (int j = 0; j < 8; j++) o = fmaf(z[j], Wm2[j * 2 + t], o);
        out[g * 2 + t] = o;
    }
}

// ---------------- host launch ----------------
extern "C" void kernel_launch(void* const* d_in, const int* in_sizes, int n_in,
                              void* d_out, int out_size) {
    const float* x    = (const float*)d_in[0];
    const int*   ei   = (const int*)d_in[1];
    const float* attr = (const float*)d_in[2];
    const int*   batch= (const int*)d_in[3];
    const float* W1A  = (const float*)d_in[4];
    const float* b1A  = (const float*)d_in[5];
    const float* W1B  = (const float*)d_in[6];
    const float* b1B  = (const float*)d_in[7];
    const float* W1C  = (const float*)d_in[8];
    const float* b1C  = (const float*)d_in[9];
    const float* W1D  = (const float*)d_in[10];
    const float* b1D  = (const float*)d_in[11];
    const float* W2   = (const float*)d_in[12];
    const float* b2   = (const float*)d_in[13];
    const float* W3   = (const float*)d_in[14];
    const float* b3   = (const float*)d_in[15];
    const float* Wm1  = (const float*)d_in[16];
    const float* bm1  = (const float*)d_in[17];
    const float* Wm2  = (const float*)d_in[18];
    const float* bm2  = (const float*)d_in[19];
    float* out = (float*)d_out;

    float *bufA, *bufB, *Wt1, *Wt2, *Wt3, *bcat;
    cudaGetSymbolAddress((void**)&bufA, g_bufA);
    cudaGetSymbolAddress((void**)&bufB, g_bufB);
    cudaGetSymbolAddress((void**)&Wt1, g_Wt1);
    cudaGetSymbolAddress((void**)&Wt2, g_Wt2);
    cudaGetSymbolAddress((void**)&Wt3, g_Wt3);
    cudaGetSymbolAddress((void**)&bcat, g_bcat);

    zero_all_k<<<(8 * NN + 255) / 256, 256>>>();
    degree_k<<<(NE + 255) / 256, 256>>>(ei, attr);
    scan_k<<<49, 1024>>>();                                      // finalize + scan fused
    scatter_k<<<(NE + 255) / 256, 256>>>(ei, attr);
    pack_k<<<(512 * 128 + 256 * 512 + 128 * 256 + 255) / 256, 256>>>(
        W1A, W1B, W1C, W1D, b1A, b1B, b1C, b1D, W2, W3);

    // LAYER 1: aggregate x once (4 heads fused, 1 warp/node) -> bufA planes [4][NN,128]
    aggx_k<<<(NN * 32 + 255) / 256, 256>>>(x, bufA);
    // 4 per-head GEMMs [NN,128]@[128,128] + bias + relu -> bufB [NN,512] concat layout
    {
        dim3 grid(4, (NN + 127) / 128);
        mma_gemm_k<<<grid, 256>>>(bufA, Wt1, bufB, NN, 128, 512,
                                  (size_t)NN * 128, bcat, 1);
    }
    // LAYER 2: GEMM [NN,512]@[512,256] -> bufA, then agg+bias+relu -> bufB
    {
        dim3 grid(2, (NN + 127) / 128);
        mma_gemm_k<<<grid, 256>>>(bufB, Wt2, bufA, NN, 512, 256, 0, nullptr, 0);
    }
    agg_uni_k<256, true><<<(NN * 32 + 255) / 256, 256>>>(bufA, bufB, b2);
    // LAYER 3: GEMM [NN,256]@[256,128] -> bufA, then agg+bias -> bufB
    {
        dim3 grid(1, (NN + 127) / 128);
        mma_gemm_k<<<grid, 256>>>(bufB, Wt3, bufA, NN, 256, 128, 0, nullptr, 0);
    }
    agg_uni_k<128, false><<<(NN * 32 + 255) / 256, 256>>>(bufA, bufB, b3);
    pool_k<<<(NN + 127) / 128, 128>>>(bufB, batch);
    final_k<<<NG, 256>>>(Wm1, bm1, Wm2, bm2, out);
}